// round 8
// baseline (speedup 1.0000x reference)
#include <cuda_runtime.h>
#include <cstdint>

#define BATCH 4
#define SEQ 2048
#define DMODEL 1024
#define NHEAD 16
#define DHEAD 64
#define MTOT (BATCH * SEQ)   // 8192

// Scratch (static device arrays: allowed; no runtime allocation)
__device__ float g_Q[MTOT * DMODEL];
__device__ float g_K[MTOT * DMODEL];
__device__ float g_V[MTOT * DMODEL];
__device__ float g_Y[MTOT * DMODEL];
__device__ float g_Xr[MTOT * DMODEL];
__device__ float g_Wqr[DMODEL * DMODEL];
__device__ float g_Wkr[DMODEL * DMODEL];
__device__ float g_Wvr[DMODEL * DMODEL];
__device__ float g_Wor[DMODEL * DMODEL];

// ---------------------------------------------------------------------------
// helpers
// ---------------------------------------------------------------------------
__device__ __forceinline__ void cp16(uint32_t dst_sh, const void* src) {
    asm volatile("cp.async.cg.shared.global [%0], [%1], 16;" :: "r"(dst_sh), "l"(src));
}
__device__ __forceinline__ void cp_commit() {
    asm volatile("cp.async.commit_group;");
}
template <int N>
__device__ __forceinline__ void cp_wait() {
    asm volatile("cp.async.wait_group %0;" :: "n"(N));
}
__device__ __forceinline__ uint32_t f2tf32(float x) {
    uint32_t u;
    asm("cvt.rna.tf32.f32 %0, %1;" : "=r"(u) : "f"(x));
    return u;
}
__device__ __forceinline__ void mma_tf32(float acc[4],
                                         const uint32_t a[4], const uint32_t b[2]) {
    asm volatile(
        "mma.sync.aligned.m16n8k8.row.col.f32.tf32.tf32.f32 "
        "{%0,%1,%2,%3}, {%4,%5,%6,%7}, {%8,%9}, {%0,%1,%2,%3};"
        : "+f"(acc[0]), "+f"(acc[1]), "+f"(acc[2]), "+f"(acc[3])
        : "r"(a[0]), "r"(a[1]), "r"(a[2]), "r"(a[3]), "r"(b[0]), "r"(b[1]));
}

// ---------------------------------------------------------------------------
// Pre-round X and all weights to tf32 (values representable in tf32, stored as
// fp32 bits). Moving the rounding upstream is bit-identical to rounding at
// fragment-load time, and removes every cvt from the GEMM/attention hot loops.
// ---------------------------------------------------------------------------
__global__ void preround_all(const float* __restrict__ X,
                             const float* __restrict__ Wq, const float* __restrict__ Wk,
                             const float* __restrict__ Wv, const float* __restrict__ Wo)
{
    const int64_t NX = (int64_t)MTOT * DMODEL / 4;     // float4 count for X
    const int64_t NW = (int64_t)DMODEL * DMODEL / 4;   // float4 count per W
    const int64_t total = NX + 4 * NW;
    for (int64_t i = (int64_t)blockIdx.x * blockDim.x + threadIdx.x;
         i < total; i += (int64_t)gridDim.x * blockDim.x) {
        const float4* src; float4* dst; int64_t j;
        if (i < NX) { src = (const float4*)X; dst = (float4*)g_Xr; j = i; }
        else {
            int64_t k = i - NX;
            int w = (int)(k / NW); j = k % NW;
            src = (const float4*)(w == 0 ? Wq : w == 1 ? Wk : w == 2 ? Wv : Wo);
            dst = (float4*)(w == 0 ? g_Wqr : w == 1 ? g_Wkr : w == 2 ? g_Wvr : g_Wor);
        }
        float4 v = src[j];
        float4 r;
        r.x = __uint_as_float(f2tf32(v.x));
        r.y = __uint_as_float(f2tf32(v.y));
        r.z = __uint_as_float(f2tf32(v.z));
        r.w = __uint_as_float(f2tf32(v.w));
        dst[j] = r;
    }
}

// ---------------------------------------------------------------------------
// tf32 GEMM: C[M,N] = A[M,K] * B[N,K]^T. Operands are PRE-ROUNDED tf32 values
// (raw bit loads, no cvt in mainloop). ROUND: round C at store (for Q/K/V/Y
// consumers); final output GEMM stores plain fp32.
// ---------------------------------------------------------------------------
template <bool ROUND>
__device__ __forceinline__ void gemm_body(
    const float* __restrict__ A, const float* __restrict__ Bw,
    float* __restrict__ C, int M, int N, int K,
    int m0, int n0, float* As, float* Bs)
{
    constexpr int BM = 128, BK = 16, PAD = 20;

    const int tid  = threadIdx.x;
    const int lane = tid & 31;
    const int warp = tid >> 5;
    const int warpM = warp >> 2;
    const int warpN = warp & 3;
    const int g  = lane >> 2;
    const int t4 = lane & 3;

    const int lrow = tid >> 2;
    const int lq   = tid & 3;

    const float* Asrc0 = A  + (size_t)(m0 + lrow)      * K + lq * 4;
    const float* Asrc1 = A  + (size_t)(m0 + lrow + 64) * K + lq * 4;
    const float* Bsrc0 = Bw + (size_t)(n0 + lrow)      * K + lq * 4;
    const float* Bsrc1 = Bw + (size_t)(n0 + lrow + 64) * K + lq * 4;

    const int dst0 = lrow * PAD + lq * 4;
    const int dst1 = (lrow + 64) * PAD + lq * 4;
    const int stage_off = BM * PAD;

    uint32_t shA[2][2], shB[2][2];
    for (int s = 0; s < 2; s++) {
        shA[s][0] = (uint32_t)__cvta_generic_to_shared(&As[s * stage_off + dst0]);
        shA[s][1] = (uint32_t)__cvta_generic_to_shared(&As[s * stage_off + dst1]);
        shB[s][0] = (uint32_t)__cvta_generic_to_shared(&Bs[s * stage_off + dst0]);
        shB[s][1] = (uint32_t)__cvta_generic_to_shared(&Bs[s * stage_off + dst1]);
    }

    float acc[16][4] = {};

    cp16(shA[0][0], Asrc0); cp16(shA[0][1], Asrc1);
    cp16(shB[0][0], Bsrc0); cp16(shB[0][1], Bsrc1);
    cp_commit();

    const int NIT = K / BK;
    int stage = 0;

    const uint32_t* a_warp_base0 = (const uint32_t*)&As[(warpM * 64) * PAD];
    const uint32_t* b_warp_base0 = (const uint32_t*)&Bs[(warpN * 32) * PAD];

    for (int it = 0; it < NIT; it++) {
        if (it + 1 < NIT) {
            const int k = (it + 1) * BK;
            const int ns = stage ^ 1;
            cp16(shA[ns][0], Asrc0 + k); cp16(shA[ns][1], Asrc1 + k);
            cp16(shB[ns][0], Bsrc0 + k); cp16(shB[ns][1], Bsrc1 + k);
            cp_commit();
            cp_wait<1>();
        } else {
            cp_wait<0>();
        }
        __syncthreads();

        const uint32_t* ab = a_warp_base0 + stage * stage_off;
        const uint32_t* bb = b_warp_base0 + stage * stage_off;

#pragma unroll
        for (int ks = 0; ks < 2; ks++) {
            const int kb = ks * 8;
            uint32_t Ar[4][4], Br[4][2];
#pragma unroll
            for (int mf = 0; mf < 4; mf++) {
                const int r = mf * 16 + g;
                Ar[mf][0] = ab[r * PAD + kb + t4];
                Ar[mf][1] = ab[(r + 8) * PAD + kb + t4];
                Ar[mf][2] = ab[r * PAD + kb + t4 + 4];
                Ar[mf][3] = ab[(r + 8) * PAD + kb + t4 + 4];
            }
#pragma unroll
            for (int nf = 0; nf < 4; nf++) {
                const int c = nf * 8 + g;
                Br[nf][0] = bb[c * PAD + kb + t4];
                Br[nf][1] = bb[c * PAD + kb + t4 + 4];
            }
#pragma unroll
            for (int mf = 0; mf < 4; mf++)
#pragma unroll
                for (int nf = 0; nf < 4; nf++)
                    mma_tf32(acc[mf * 4 + nf], Ar[mf], Br[nf]);
        }
        __syncthreads();
        stage ^= 1;
    }

#pragma unroll
    for (int mf = 0; mf < 4; mf++) {
#pragma unroll
        for (int nf = 0; nf < 4; nf++) {
            const int idx = mf * 4 + nf;
            const int row = m0 + warpM * 64 + mf * 16 + g;
            const int col = n0 + warpN * 32 + nf * 8 + t4 * 2;
            float c0 = acc[idx][0], c1 = acc[idx][1];
            float c2 = acc[idx][2], c3 = acc[idx][3];
            if (ROUND) {
                c0 = __uint_as_float(f2tf32(c0));
                c1 = __uint_as_float(f2tf32(c1));
                c2 = __uint_as_float(f2tf32(c2));
                c3 = __uint_as_float(f2tf32(c3));
            }
            *(float2*)&C[(size_t)row * N + col]       = make_float2(c0, c1);
            *(float2*)&C[(size_t)(row + 8) * N + col] = make_float2(c2, c3);
        }
    }
}

// Fused Q/K/V projections (writes rounded outputs for the attention kernel).
__global__ __launch_bounds__(256) void gemm_tf32_qkv(
    float* __restrict__ Qo, float* __restrict__ Ko, float* __restrict__ Vo)
{
    __shared__ float As[2 * 128 * 20];
    __shared__ float Bs[2 * 128 * 20];
    const int z = blockIdx.z;
    const float* Bw = (z == 0) ? g_Wqr : (z == 1) ? g_Wkr : g_Wvr;
    float* C = (z == 0) ? Qo : (z == 1) ? Ko : Vo;
    gemm_body<true>(g_Xr, Bw, C, MTOT, DMODEL, DMODEL,
                    blockIdx.y * 128, blockIdx.x * 128, As, Bs);
}

// Output projection (plain fp32 store).
__global__ __launch_bounds__(256) void gemm_tf32_out(
    const float* __restrict__ A, float* __restrict__ C)
{
    __shared__ float As[2 * 128 * 20];
    __shared__ float Bs[2 * 128 * 20];
    gemm_body<false>(A, g_Wor, C, MTOT, DMODEL, DMODEL,
                     blockIdx.y * 128, blockIdx.x * 128, As, Bs);
}

// ---------------------------------------------------------------------------
// Tensor-core flash attention. Inputs Q/K/V are pre-rounded tf32 values.
// K smem: column-pair packed uint2 (c, c+4), row stride 36 uint2 -> B-frag
// reads are single LDS.64, conflict-free (bank = 8g + 2t4 per 16-lane phase).
// V smem: row-pair packed uint2 (r, r+4) with rot2 column permutation,
// row stride 68 uint2 -> LDS.64 reads conflict-free (bank = 8t4 + 2g).
// ---------------------------------------------------------------------------
#define KPS2 36   // Kp row stride, uint2 units (72 words)
#define VPS2 68   // Vp packed-row stride, uint2 units (136 words); % 16 == 4
#define PSS  68   // Ps row stride, floats
#define ATTN_SMEM_BYTES (64 * KPS2 * 8 + 32 * VPS2 * 8 + 128 * PSS * 4)

__device__ __forceinline__ int rot2(int c) { return ((c << 2) & 63) | (c >> 4); }

__global__ __launch_bounds__(256, 2) void attn_mma(
    const float* __restrict__ Q, const float* __restrict__ K,
    const float* __restrict__ V, float* __restrict__ Y)
{
    extern __shared__ float sm[];
    uint2* Kp = (uint2*)sm;                       // [64][36] uint2
    uint2* Vp = Kp + 64 * KPS2;                   // [32][68] uint2
    float* Ps = (float*)(Vp + 32 * VPS2);         // [128][68] floats

    const int tid  = threadIdx.x;
    const int lane = tid & 31;
    const int warp = tid >> 5;
    const int g  = lane >> 2;   // 0..7
    const int t4 = lane & 3;    // 0..3
    const int mrow = warp * 16;

    const int qt = blockIdx.x;
    const int h  = blockIdx.y;
    const int b  = blockIdx.z;
    const size_t base = (size_t)b * SEQ * DMODEL + (size_t)h * DHEAD;

    // ---- Stage Q tile (128x64, pre-scaled by 1/8 — exact on tf32 values) ----
    {
        const int r = tid >> 1;
        const int c0 = (tid & 1) * 32;
        const float* src = &Q[base + (size_t)(qt * 128 + r) * DMODEL + c0];
#pragma unroll
        for (int i = 0; i < 8; i++) {
            float4 v = *(const float4*)(src + i * 4);
            Ps[r * PSS + c0 + i * 4 + 0] = v.x * 0.125f;
            Ps[r * PSS + c0 + i * 4 + 1] = v.y * 0.125f;
            Ps[r * PSS + c0 + i * 4 + 2] = v.z * 0.125f;
            Ps[r * PSS + c0 + i * 4 + 3] = v.w * 0.125f;
        }
    }
    __syncthreads();

    uint32_t qf[8][4];
#pragma unroll
    for (int kb = 0; kb < 8; kb++) {
        qf[kb][0] = __float_as_uint(Ps[(mrow + g) * PSS + kb * 8 + t4]);
        qf[kb][1] = __float_as_uint(Ps[(mrow + g + 8) * PSS + kb * 8 + t4]);
        qf[kb][2] = __float_as_uint(Ps[(mrow + g) * PSS + kb * 8 + t4 + 4]);
        qf[kb][3] = __float_as_uint(Ps[(mrow + g + 8) * PSS + kb * 8 + t4 + 4]);
    }
    __syncthreads();   // Ps free for reuse as P buffer

    // Precompute permuted V columns for this thread's 8 nf-fragments.
    int vcol[8];
#pragma unroll
    for (int nf = 0; nf < 8; nf++) vcol[nf] = rot2(nf * 8 + g);

    float o[8][4] = {};
    float m0r = -1e30f, m1r = -1e30f;
    float l0 = 0.0f, l1 = 0.0f;

    const int lrow = tid >> 2;         // 0..63
    const int lq   = (tid & 3) * 16;   // 0,16,32,48
    const int kbA  = lq >> 3;          // first kb group this thread loads
    // V packed-row coords for this thread's global row:
    const int vpr  = (lrow >> 3) * 4 + (lrow & 3);
    const int voff = (lrow >> 2) & 1;

    for (int kt = 0; kt < SEQ / 64; kt++) {
        // ---- Load K,V tile (raw tf32 bits), store packed ----
        {
            const uint4* Kg = (const uint4*)&K[base + (size_t)(kt * 64 + lrow) * DMODEL + lq];
            const uint4* Vg = (const uint4*)&V[base + (size_t)(kt * 64 + lrow) * DMODEL + lq];
            uint4 kr[4], vr[4];
#pragma unroll
            for (int i = 0; i < 4; i++) { kr[i] = Kg[i]; vr[i] = Vg[i]; }
            const uint32_t* ka = (const uint32_t*)kr;
            const uint32_t* va = (const uint32_t*)vr;
            // K: pack column pairs (c, c+4) within each 8-col group
#pragma unroll
            for (int j = 0; j < 2; j++)
#pragma unroll
                for (int pc = 0; pc < 4; pc++)
                    Kp[lrow * KPS2 + (kbA + j) * 4 + pc] =
                        make_uint2(ka[j * 8 + pc], ka[j * 8 + pc + 4]);
            // V: scatter 32-bit halves into row-pair packed layout
            uint32_t* Vw = (uint32_t*)Vp;
#pragma unroll
            for (int c = 0; c < 16; c++)
                Vw[2 * (vpr * VPS2 + 4 * c + (lq >> 4)) + voff] = va[c];
        }
        __syncthreads();

        // ---- S = Qs @ K^T  (16x64 per warp) ----
        float sacc[8][4] = {};
#pragma unroll
        for (int kb = 0; kb < 8; kb++) {
#pragma unroll
            for (int nf = 0; nf < 8; nf++) {
                uint2 kk2 = Kp[(nf * 8 + g) * KPS2 + kb * 4 + t4];
                uint32_t bf[2] = { kk2.x, kk2.y };
                mma_tf32(sacc[nf], qf[kb], bf);
            }
        }

        // ---- online softmax ----
        float rmax0 = -1e30f, rmax1 = -1e30f;
#pragma unroll
        for (int nf = 0; nf < 8; nf++) {
            rmax0 = fmaxf(rmax0, fmaxf(sacc[nf][0], sacc[nf][1]));
            rmax1 = fmaxf(rmax1, fmaxf(sacc[nf][2], sacc[nf][3]));
        }
        rmax0 = fmaxf(rmax0, __shfl_xor_sync(0xffffffffu, rmax0, 1));
        rmax0 = fmaxf(rmax0, __shfl_xor_sync(0xffffffffu, rmax0, 2));
        rmax1 = fmaxf(rmax1, __shfl_xor_sync(0xffffffffu, rmax1, 1));
        rmax1 = fmaxf(rmax1, __shfl_xor_sync(0xffffffffu, rmax1, 2));

        const float mnew0 = fmaxf(m0r, rmax0);
        const float mnew1 = fmaxf(m1r, rmax1);
        const float a0 = __expf(m0r - mnew0);
        const float a1 = __expf(m1r - mnew1);
        m0r = mnew0; m1r = mnew1;
        l0 *= a0;    l1 *= a1;

        float ps0 = 0.0f, ps1 = 0.0f;
#pragma unroll
        for (int nf = 0; nf < 8; nf++) {
            float p0 = __expf(sacc[nf][0] - m0r);
            float p1 = __expf(sacc[nf][1] - m0r);
            float p2 = __expf(sacc[nf][2] - m1r);
            float p3 = __expf(sacc[nf][3] - m1r);
            ps0 += p0 + p1;
            ps1 += p2 + p3;
            *(float2*)&Ps[(mrow + g) * PSS + nf * 8 + 2 * t4]     = make_float2(p0, p1);
            *(float2*)&Ps[(mrow + g + 8) * PSS + nf * 8 + 2 * t4] = make_float2(p2, p3);
            o[nf][0] *= a0; o[nf][1] *= a0;
            o[nf][2] *= a1; o[nf][3] *= a1;
        }
        l0 += ps0; l1 += ps1;
        __syncwarp();   // P visible to own warp (only own rows are read)

        // ---- O += P @ V ----
#pragma unroll
        for (int kk = 0; kk < 8; kk++) {
            uint32_t pf[4];
            pf[0] = f2tf32(Ps[(mrow + g) * PSS + kk * 8 + t4]);
            pf[1] = f2tf32(Ps[(mrow + g + 8) * PSS + kk * 8 + t4]);
            pf[2] = f2tf32(Ps[(mrow + g) * PSS + kk * 8 + t4 + 4]);
            pf[3] = f2tf32(Ps[(mrow + g + 8) * PSS + kk * 8 + t4 + 4]);
#pragma unroll
            for (int nf = 0; nf < 8; nf++) {
                uint2 vv2 = Vp[(kk * 4 + t4) * VPS2 + vcol[nf]];
                uint32_t vf[2] = { vv2.x, vv2.y };
                mma_tf32(o[nf], pf, vf);
            }
        }
        __syncthreads();   // K/V reads done before next iter overwrites
    }

    // ---- finalize: reduce l across quad, normalize, write out (rounded) ----
    l0 += __shfl_xor_sync(0xffffffffu, l0, 1);
    l0 += __shfl_xor_sync(0xffffffffu, l0, 2);
    l1 += __shfl_xor_sync(0xffffffffu, l1, 1);
    l1 += __shfl_xor_sync(0xffffffffu, l1, 2);
    const float inv0 = 1.0f / l0;
    const float inv1 = 1.0f / l1;

    const int row0 = qt * 128 + mrow + g;
#pragma unroll
    for (int nf = 0; nf < 8; nf++) {
        const int col = nf * 8 + 2 * t4;
        *(float2*)&Y[base + (size_t)row0 * DMODEL + col] = make_float2(
            __uint_as_float(f2tf32(o[nf][0] * inv0)),
            __uint_as_float(f2tf32(o[nf][1] * inv0)));
        *(float2*)&Y[base + (size_t)(row0 + 8) * DMODEL + col] = make_float2(
            __uint_as_float(f2tf32(o[nf][2] * inv1)),
            __uint_as_float(f2tf32(o[nf][3] * inv1)));
    }
}

// ---------------------------------------------------------------------------
extern "C" void kernel_launch(void* const* d_in, const int* in_sizes, int n_in,
                              void* d_out, int out_size)
{
    const float* X  = (const float*)d_in[0];
    const float* Wq = (const float*)d_in[1];
    const float* Wk = (const float*)d_in[2];
    const float* Wv = (const float*)d_in[3];
    const float* Wo = (const float*)d_in[4];
    float* out = (float*)d_out;

    float *pQ, *pK, *pV, *pY;
    cudaGetSymbolAddress((void**)&pQ, g_Q);
    cudaGetSymbolAddress((void**)&pK, g_K);
    cudaGetSymbolAddress((void**)&pV, g_V);
    cudaGetSymbolAddress((void**)&pY, g_Y);

    cudaFuncSetAttribute(attn_mma, cudaFuncAttributeMaxDynamicSharedMemorySize,
                         ATTN_SMEM_BYTES);

    preround_all<<<1024, 256>>>(X, Wq, Wk, Wv, Wo);

    dim3 gQKV(DMODEL / 128, MTOT / 128, 3);  // (8, 64, 3)
    gemm_tf32_qkv<<<gQKV, 256>>>(pQ, pK, pV);

    dim3 gAttn(SEQ / 128, NHEAD, BATCH);     // (16, 16, 4)
    attn_mma<<<gAttn, 256, ATTN_SMEM_BYTES>>>(pQ, pK, pV, pY);

    dim3 gGemm(DMODEL / 128, MTOT / 128);    // (8, 64)
    gemm_tf32_out<<<gGemm, 256>>>(pY, out);
}

// round 9
// speedup vs baseline: 1.0108x; 1.0108x over previous
#include <cuda_runtime.h>
#include <cstdint>

#define BATCH 4
#define SEQ 2048
#define DMODEL 1024
#define NHEAD 16
#define DHEAD 64
#define MTOT (BATCH * SEQ)   // 8192

// Scratch (static device arrays: allowed; no runtime allocation)
__device__ float g_Q[MTOT * DMODEL];
__device__ float g_K[MTOT * DMODEL];
__device__ float g_V[MTOT * DMODEL];
__device__ float g_Y[MTOT * DMODEL];

// ---------------------------------------------------------------------------
// helpers
// ---------------------------------------------------------------------------
__device__ __forceinline__ void cp16(uint32_t dst_sh, const void* src) {
    asm volatile("cp.async.cg.shared.global [%0], [%1], 16;" :: "r"(dst_sh), "l"(src));
}
__device__ __forceinline__ void cp_commit() {
    asm volatile("cp.async.commit_group;");
}
template <int N>
__device__ __forceinline__ void cp_wait() {
    asm volatile("cp.async.wait_group %0;" :: "n"(N));
}
__device__ __forceinline__ uint32_t f2tf32(float x) {
    uint32_t u;
    asm("cvt.rna.tf32.f32 %0, %1;" : "=r"(u) : "f"(x));
    return u;
}
__device__ __forceinline__ void mma_tf32(float acc[4],
                                         const uint32_t a[4], const uint32_t b[2]) {
    asm volatile(
        "mma.sync.aligned.m16n8k8.row.col.f32.tf32.tf32.f32 "
        "{%0,%1,%2,%3}, {%4,%5,%6,%7}, {%8,%9}, {%0,%1,%2,%3};"
        : "+f"(acc[0]), "+f"(acc[1]), "+f"(acc[2]), "+f"(acc[3])
        : "r"(a[0]), "r"(a[1]), "r"(a[2]), "r"(a[3]), "r"(b[0]), "r"(b[1]));
}

// ---------------------------------------------------------------------------
// tf32 GEMM mainloop (R7 form: fp32 smem, cvt at fragment read — measured
// fastest). ROUND: round C to tf32 values at store, so downstream kernels can
// load raw bits (bit-identical to rounding at their fragment loads).
// ---------------------------------------------------------------------------
template <bool ROUND>
__device__ __forceinline__ void gemm_body(
    const float* __restrict__ A, const float* __restrict__ Bw,
    float* __restrict__ C, int M, int N, int K,
    int m0, int n0, float* As, float* Bs)
{
    constexpr int BM = 128, BK = 16, PAD = 20;

    const int tid  = threadIdx.x;
    const int lane = tid & 31;
    const int warp = tid >> 5;
    const int warpM = warp >> 2;
    const int warpN = warp & 3;
    const int g  = lane >> 2;
    const int t4 = lane & 3;

    const int lrow = tid >> 2;
    const int lq   = tid & 3;

    const float* Asrc0 = A  + (size_t)(m0 + lrow)      * K + lq * 4;
    const float* Asrc1 = A  + (size_t)(m0 + lrow + 64) * K + lq * 4;
    const float* Bsrc0 = Bw + (size_t)(n0 + lrow)      * K + lq * 4;
    const float* Bsrc1 = Bw + (size_t)(n0 + lrow + 64) * K + lq * 4;

    const int dst0 = lrow * PAD + lq * 4;
    const int dst1 = (lrow + 64) * PAD + lq * 4;
    const int stage_off = BM * PAD;

    uint32_t shA[2][2], shB[2][2];
    for (int s = 0; s < 2; s++) {
        shA[s][0] = (uint32_t)__cvta_generic_to_shared(&As[s * stage_off + dst0]);
        shA[s][1] = (uint32_t)__cvta_generic_to_shared(&As[s * stage_off + dst1]);
        shB[s][0] = (uint32_t)__cvta_generic_to_shared(&Bs[s * stage_off + dst0]);
        shB[s][1] = (uint32_t)__cvta_generic_to_shared(&Bs[s * stage_off + dst1]);
    }

    float acc[16][4] = {};

    cp16(shA[0][0], Asrc0); cp16(shA[0][1], Asrc1);
    cp16(shB[0][0], Bsrc0); cp16(shB[0][1], Bsrc1);
    cp_commit();

    const int NIT = K / BK;
    int stage = 0;

    const float* a_warp_base0 = &As[(warpM * 64) * PAD];
    const float* b_warp_base0 = &Bs[(warpN * 32) * PAD];

    for (int it = 0; it < NIT; it++) {
        if (it + 1 < NIT) {
            const int k = (it + 1) * BK;
            const int ns = stage ^ 1;
            cp16(shA[ns][0], Asrc0 + k); cp16(shA[ns][1], Asrc1 + k);
            cp16(shB[ns][0], Bsrc0 + k); cp16(shB[ns][1], Bsrc1 + k);
            cp_commit();
            cp_wait<1>();
        } else {
            cp_wait<0>();
        }
        __syncthreads();

        const float* ab = a_warp_base0 + stage * stage_off;
        const float* bb = b_warp_base0 + stage * stage_off;

#pragma unroll
        for (int ks = 0; ks < 2; ks++) {
            const int kb = ks * 8;
            uint32_t Ar[4][4], Br[4][2];
#pragma unroll
            for (int mf = 0; mf < 4; mf++) {
                const int r = mf * 16 + g;
                Ar[mf][0] = f2tf32(ab[r * PAD + kb + t4]);
                Ar[mf][1] = f2tf32(ab[(r + 8) * PAD + kb + t4]);
                Ar[mf][2] = f2tf32(ab[r * PAD + kb + t4 + 4]);
                Ar[mf][3] = f2tf32(ab[(r + 8) * PAD + kb + t4 + 4]);
            }
#pragma unroll
            for (int nf = 0; nf < 4; nf++) {
                const int c = nf * 8 + g;
                Br[nf][0] = f2tf32(bb[c * PAD + kb + t4]);
                Br[nf][1] = f2tf32(bb[c * PAD + kb + t4 + 4]);
            }
#pragma unroll
            for (int mf = 0; mf < 4; mf++)
#pragma unroll
                for (int nf = 0; nf < 4; nf++)
                    mma_tf32(acc[mf * 4 + nf], Ar[mf], Br[nf]);
        }
        __syncthreads();
        stage ^= 1;
    }

#pragma unroll
    for (int mf = 0; mf < 4; mf++) {
#pragma unroll
        for (int nf = 0; nf < 4; nf++) {
            const int idx = mf * 4 + nf;
            const int row = m0 + warpM * 64 + mf * 16 + g;
            const int col = n0 + warpN * 32 + nf * 8 + t4 * 2;
            float c0 = acc[idx][0], c1 = acc[idx][1];
            float c2 = acc[idx][2], c3 = acc[idx][3];
            if (ROUND) {
                c0 = __uint_as_float(f2tf32(c0));
                c1 = __uint_as_float(f2tf32(c1));
                c2 = __uint_as_float(f2tf32(c2));
                c3 = __uint_as_float(f2tf32(c3));
            }
            *(float2*)&C[(size_t)row * N + col]       = make_float2(c0, c1);
            *(float2*)&C[(size_t)(row + 8) * N + col] = make_float2(c2, c3);
        }
    }
}

// Fused Q/K/V projections: rounds outputs to tf32 values for attention.
__global__ __launch_bounds__(256) void gemm_tf32_qkv(
    const float* __restrict__ X,
    const float* __restrict__ Wq, const float* __restrict__ Wk,
    const float* __restrict__ Wv,
    float* __restrict__ Qo, float* __restrict__ Ko, float* __restrict__ Vo)
{
    __shared__ float As[2 * 128 * 20];
    __shared__ float Bs[2 * 128 * 20];
    const int z = blockIdx.z;
    const float* Bw = (z == 0) ? Wq : (z == 1) ? Wk : Wv;
    float* C = (z == 0) ? Qo : (z == 1) ? Ko : Vo;
    gemm_body<true>(X, Bw, C, MTOT, DMODEL, DMODEL,
                    blockIdx.y * 128, blockIdx.x * 128, As, Bs);
}

// Output projection (plain fp32 store).
__global__ __launch_bounds__(256) void gemm_tf32_out(
    const float* __restrict__ A, const float* __restrict__ Bw,
    float* __restrict__ C)
{
    __shared__ float As[2 * 128 * 20];
    __shared__ float Bs[2 * 128 * 20];
    gemm_body<false>(A, Bw, C, MTOT, DMODEL, DMODEL,
                     blockIdx.y * 128, blockIdx.x * 128, As, Bs);
}

// ---------------------------------------------------------------------------
// Tensor-core flash attention. Inputs Q/K/V are tf32-valued (rounded by the
// QKV epilogue) -> fragment loads are raw bits.
// K smem: column-pair packed uint2 (c, c+4), row stride 36 uint2 -> B-frag
// reads are single LDS.64, conflict-free. V smem: row-pair packed uint2
// (r, r+4) with rot2 column permutation, stride 68 uint2 -> LDS.64 reads
// conflict-free.
// ---------------------------------------------------------------------------
#define KPS2 36   // Kp row stride, uint2 units (72 words)
#define VPS2 68   // Vp packed-row stride, uint2 units (136 words); % 16 == 4
#define PSS  68   // Ps row stride, floats
#define ATTN_SMEM_BYTES (64 * KPS2 * 8 + 32 * VPS2 * 8 + 128 * PSS * 4)

__device__ __forceinline__ int rot2(int c) { return ((c << 2) & 63) | (c >> 4); }

__global__ __launch_bounds__(256, 2) void attn_mma(
    const float* __restrict__ Q, const float* __restrict__ K,
    const float* __restrict__ V, float* __restrict__ Y)
{
    extern __shared__ float sm[];
    uint2* Kp = (uint2*)sm;                       // [64][36] uint2
    uint2* Vp = Kp + 64 * KPS2;                   // [32][68] uint2
    float* Ps = (float*)(Vp + 32 * VPS2);         // [128][68] floats

    const int tid  = threadIdx.x;
    const int lane = tid & 31;
    const int warp = tid >> 5;
    const int g  = lane >> 2;   // 0..7
    const int t4 = lane & 3;    // 0..3
    const int mrow = warp * 16;

    const int qt = blockIdx.x;
    const int h  = blockIdx.y;
    const int b  = blockIdx.z;
    const size_t base = (size_t)b * SEQ * DMODEL + (size_t)h * DHEAD;

    // ---- Stage Q tile (128x64, pre-scaled by 1/8 — exact on tf32 values) ----
    {
        const int r = tid >> 1;
        const int c0 = (tid & 1) * 32;
        const float* src = &Q[base + (size_t)(qt * 128 + r) * DMODEL + c0];
#pragma unroll
        for (int i = 0; i < 8; i++) {
            float4 v = *(const float4*)(src + i * 4);
            Ps[r * PSS + c0 + i * 4 + 0] = v.x * 0.125f;
            Ps[r * PSS + c0 + i * 4 + 1] = v.y * 0.125f;
            Ps[r * PSS + c0 + i * 4 + 2] = v.z * 0.125f;
            Ps[r * PSS + c0 + i * 4 + 3] = v.w * 0.125f;
        }
    }
    __syncthreads();

    uint32_t qf[8][4];
#pragma unroll
    for (int kb = 0; kb < 8; kb++) {
        qf[kb][0] = __float_as_uint(Ps[(mrow + g) * PSS + kb * 8 + t4]);
        qf[kb][1] = __float_as_uint(Ps[(mrow + g + 8) * PSS + kb * 8 + t4]);
        qf[kb][2] = __float_as_uint(Ps[(mrow + g) * PSS + kb * 8 + t4 + 4]);
        qf[kb][3] = __float_as_uint(Ps[(mrow + g + 8) * PSS + kb * 8 + t4 + 4]);
    }
    __syncthreads();   // Ps free for reuse as P buffer

    int vcol[8];
#pragma unroll
    for (int nf = 0; nf < 8; nf++) vcol[nf] = rot2(nf * 8 + g);

    float o[8][4] = {};
    float m0r = -1e30f, m1r = -1e30f;
    float l0 = 0.0f, l1 = 0.0f;

    const int lrow = tid >> 2;         // 0..63
    const int lq   = (tid & 3) * 16;   // 0,16,32,48
    const int kbA  = lq >> 3;
    const int vpr  = (lrow >> 3) * 4 + (lrow & 3);
    const int voff = (lrow >> 2) & 1;

    for (int kt = 0; kt < SEQ / 64; kt++) {
        // ---- Load K,V tile (raw tf32 bits), store packed ----
        {
            const uint4* Kg = (const uint4*)&K[base + (size_t)(kt * 64 + lrow) * DMODEL + lq];
            const uint4* Vg = (const uint4*)&V[base + (size_t)(kt * 64 + lrow) * DMODEL + lq];
            uint4 kr[4], vr[4];
#pragma unroll
            for (int i = 0; i < 4; i++) { kr[i] = Kg[i]; vr[i] = Vg[i]; }
            const uint32_t* ka = (const uint32_t*)kr;
            const uint32_t* va = (const uint32_t*)vr;
#pragma unroll
            for (int j = 0; j < 2; j++)
#pragma unroll
                for (int pc = 0; pc < 4; pc++)
                    Kp[lrow * KPS2 + (kbA + j) * 4 + pc] =
                        make_uint2(ka[j * 8 + pc], ka[j * 8 + pc + 4]);
            uint32_t* Vw = (uint32_t*)Vp;
#pragma unroll
            for (int c = 0; c < 16; c++)
                Vw[2 * (vpr * VPS2 + 4 * c + (lq >> 4)) + voff] = va[c];
        }
        __syncthreads();

        // ---- S = Qs @ K^T ----
        float sacc[8][4] = {};
#pragma unroll
        for (int kb = 0; kb < 8; kb++) {
#pragma unroll
            for (int nf = 0; nf < 8; nf++) {
                uint2 kk2 = Kp[(nf * 8 + g) * KPS2 + kb * 4 + t4];
                uint32_t bf[2] = { kk2.x, kk2.y };
                mma_tf32(sacc[nf], qf[kb], bf);
            }
        }

        // ---- online softmax ----
        float rmax0 = -1e30f, rmax1 = -1e30f;
#pragma unroll
        for (int nf = 0; nf < 8; nf++) {
            rmax0 = fmaxf(rmax0, fmaxf(sacc[nf][0], sacc[nf][1]));
            rmax1 = fmaxf(rmax1, fmaxf(sacc[nf][2], sacc[nf][3]));
        }
        rmax0 = fmaxf(rmax0, __shfl_xor_sync(0xffffffffu, rmax0, 1));
        rmax0 = fmaxf(rmax0, __shfl_xor_sync(0xffffffffu, rmax0, 2));
        rmax1 = fmaxf(rmax1, __shfl_xor_sync(0xffffffffu, rmax1, 1));
        rmax1 = fmaxf(rmax1, __shfl_xor_sync(0xffffffffu, rmax1, 2));

        const float mnew0 = fmaxf(m0r, rmax0);
        const float mnew1 = fmaxf(m1r, rmax1);
        const float a0 = __expf(m0r - mnew0);
        const float a1 = __expf(m1r - mnew1);
        m0r = mnew0; m1r = mnew1;
        l0 *= a0;    l1 *= a1;

        float ps0 = 0.0f, ps1 = 0.0f;
#pragma unroll
        for (int nf = 0; nf < 8; nf++) {
            float p0 = __expf(sacc[nf][0] - m0r);
            float p1 = __expf(sacc[nf][1] - m0r);
            float p2 = __expf(sacc[nf][2] - m1r);
            float p3 = __expf(sacc[nf][3] - m1r);
            ps0 += p0 + p1;
            ps1 += p2 + p3;
            *(float2*)&Ps[(mrow + g) * PSS + nf * 8 + 2 * t4]     = make_float2(p0, p1);
            *(float2*)&Ps[(mrow + g + 8) * PSS + nf * 8 + 2 * t4] = make_float2(p2, p3);
            o[nf][0] *= a0; o[nf][1] *= a0;
            o[nf][2] *= a1; o[nf][3] *= a1;
        }
        l0 += ps0; l1 += ps1;
        __syncwarp();   // P visible to own warp (only own rows are read)

        // ---- O += P @ V ----
#pragma unroll
        for (int kk = 0; kk < 8; kk++) {
            uint32_t pf[4];
            pf[0] = f2tf32(Ps[(mrow + g) * PSS + kk * 8 + t4]);
            pf[1] = f2tf32(Ps[(mrow + g + 8) * PSS + kk * 8 + t4]);
            pf[2] = f2tf32(Ps[(mrow + g) * PSS + kk * 8 + t4 + 4]);
            pf[3] = f2tf32(Ps[(mrow + g + 8) * PSS + kk * 8 + t4 + 4]);
#pragma unroll
            for (int nf = 0; nf < 8; nf++) {
                uint2 vv2 = Vp[(kk * 4 + t4) * VPS2 + vcol[nf]];
                uint32_t vf[2] = { vv2.x, vv2.y };
                mma_tf32(o[nf], pf, vf);
            }
        }
        __syncthreads();   // K/V reads done before next iter overwrites
    }

    // ---- finalize ----
    l0 += __shfl_xor_sync(0xffffffffu, l0, 1);
    l0 += __shfl_xor_sync(0xffffffffu, l0, 2);
    l1 += __shfl_xor_sync(0xffffffffu, l1, 1);
    l1 += __shfl_xor_sync(0xffffffffu, l1, 2);
    const float inv0 = 1.0f / l0;
    const float inv1 = 1.0f / l1;

    const int row0 = qt * 128 + mrow + g;
#pragma unroll
    for (int nf = 0; nf < 8; nf++) {
        const int col = nf * 8 + 2 * t4;
        *(float2*)&Y[base + (size_t)row0 * DMODEL + col] =
            make_float2(o[nf][0] * inv0, o[nf][1] * inv0);
        *(float2*)&Y[base + (size_t)(row0 + 8) * DMODEL + col] =
            make_float2(o[nf][2] * inv1, o[nf][3] * inv1);
    }
}

// ---------------------------------------------------------------------------
extern "C" void kernel_launch(void* const* d_in, const int* in_sizes, int n_in,
                              void* d_out, int out_size)
{
    const float* X  = (const float*)d_in[0];
    const float* Wq = (const float*)d_in[1];
    const float* Wk = (const float*)d_in[2];
    const float* Wv = (const float*)d_in[3];
    const float* Wo = (const float*)d_in[4];
    float* out = (float*)d_out;

    float *pQ, *pK, *pV, *pY;
    cudaGetSymbolAddress((void**)&pQ, g_Q);
    cudaGetSymbolAddress((void**)&pK, g_K);
    cudaGetSymbolAddress((void**)&pV, g_V);
    cudaGetSymbolAddress((void**)&pY, g_Y);

    cudaFuncSetAttribute(attn_mma, cudaFuncAttributeMaxDynamicSharedMemorySize,
                         ATTN_SMEM_BYTES);

    dim3 gQKV(DMODEL / 128, MTOT / 128, 3);  // (8, 64, 3)
    gemm_tf32_qkv<<<gQKV, 256>>>(X, Wq, Wk, Wv, pQ, pK, pV);

    dim3 gAttn(SEQ / 128, NHEAD, BATCH);     // (16, 16, 4)
    attn_mma<<<gAttn, 256, ATTN_SMEM_BYTES>>>(pQ, pK, pV, pY);

    dim3 gGemm(DMODEL / 128, MTOT / 128);    // (8, 64)
    gemm_tf32_out<<<gGemm, 256>>>(pY, Wo, out);
}

// round 10
// speedup vs baseline: 1.1423x; 1.1301x over previous
#include <cuda_runtime.h>
#include <cstdint>

#define BATCH 4
#define SEQ 2048
#define DMODEL 1024
#define NHEAD 16
#define DHEAD 64
#define MTOT (BATCH * SEQ)   // 8192

// Scratch (static device arrays: allowed; no runtime allocation)
__device__ float g_Q[MTOT * DMODEL];
__device__ float g_K[MTOT * DMODEL];
__device__ float g_V[MTOT * DMODEL];
__device__ float g_Y[MTOT * DMODEL];

// ---------------------------------------------------------------------------
// helpers
// ---------------------------------------------------------------------------
__device__ __forceinline__ void cp16(uint32_t dst_sh, const void* src) {
    asm volatile("cp.async.cg.shared.global [%0], [%1], 16;" :: "r"(dst_sh), "l"(src));
}
__device__ __forceinline__ void cp_commit() {
    asm volatile("cp.async.commit_group;");
}
template <int N>
__device__ __forceinline__ void cp_wait() {
    asm volatile("cp.async.wait_group %0;" :: "n"(N));
}
__device__ __forceinline__ uint32_t f2tf32(float x) {
    uint32_t u;
    asm("cvt.rna.tf32.f32 %0, %1;" : "=r"(u) : "f"(x));
    return u;
}
__device__ __forceinline__ void mma_tf32(float acc[4],
                                         const uint32_t a[4], const uint32_t b[2]) {
    asm volatile(
        "mma.sync.aligned.m16n8k8.row.col.f32.tf32.tf32.f32 "
        "{%0,%1,%2,%3}, {%4,%5,%6,%7}, {%8,%9}, {%0,%1,%2,%3};"
        : "+f"(acc[0]), "+f"(acc[1]), "+f"(acc[2]), "+f"(acc[3])
        : "r"(a[0]), "r"(a[1]), "r"(a[2]), "r"(a[3]), "r"(b[0]), "r"(b[1]));
}

// ---------------------------------------------------------------------------
// tf32 GEMM mainloop (R7 form: fp32 smem, cvt at fragment read — measured
// fastest). ROUND: round C to tf32 values at store, so downstream kernels can
// load raw bits (bit-identical to rounding at their fragment loads).
// ---------------------------------------------------------------------------
template <bool ROUND>
__device__ __forceinline__ void gemm_body(
    const float* __restrict__ A, const float* __restrict__ Bw,
    float* __restrict__ C, int M, int N, int K,
    int m0, int n0, float* As, float* Bs)
{
    constexpr int BM = 128, BK = 16, PAD = 20;

    const int tid  = threadIdx.x;
    const int lane = tid & 31;
    const int warp = tid >> 5;
    const int warpM = warp >> 2;
    const int warpN = warp & 3;
    const int g  = lane >> 2;
    const int t4 = lane & 3;

    const int lrow = tid >> 2;
    const int lq   = tid & 3;

    const float* Asrc0 = A  + (size_t)(m0 + lrow)      * K + lq * 4;
    const float* Asrc1 = A  + (size_t)(m0 + lrow + 64) * K + lq * 4;
    const float* Bsrc0 = Bw + (size_t)(n0 + lrow)      * K + lq * 4;
    const float* Bsrc1 = Bw + (size_t)(n0 + lrow + 64) * K + lq * 4;

    const int dst0 = lrow * PAD + lq * 4;
    const int dst1 = (lrow + 64) * PAD + lq * 4;
    const int stage_off = BM * PAD;

    uint32_t shA[2][2], shB[2][2];
    for (int s = 0; s < 2; s++) {
        shA[s][0] = (uint32_t)__cvta_generic_to_shared(&As[s * stage_off + dst0]);
        shA[s][1] = (uint32_t)__cvta_generic_to_shared(&As[s * stage_off + dst1]);
        shB[s][0] = (uint32_t)__cvta_generic_to_shared(&Bs[s * stage_off + dst0]);
        shB[s][1] = (uint32_t)__cvta_generic_to_shared(&Bs[s * stage_off + dst1]);
    }

    float acc[16][4] = {};

    cp16(shA[0][0], Asrc0); cp16(shA[0][1], Asrc1);
    cp16(shB[0][0], Bsrc0); cp16(shB[0][1], Bsrc1);
    cp_commit();

    const int NIT = K / BK;
    int stage = 0;

    const float* a_warp_base0 = &As[(warpM * 64) * PAD];
    const float* b_warp_base0 = &Bs[(warpN * 32) * PAD];

    for (int it = 0; it < NIT; it++) {
        if (it + 1 < NIT) {
            const int k = (it + 1) * BK;
            const int ns = stage ^ 1;
            cp16(shA[ns][0], Asrc0 + k); cp16(shA[ns][1], Asrc1 + k);
            cp16(shB[ns][0], Bsrc0 + k); cp16(shB[ns][1], Bsrc1 + k);
            cp_commit();
            cp_wait<1>();
        } else {
            cp_wait<0>();
        }
        __syncthreads();

        const float* ab = a_warp_base0 + stage * stage_off;
        const float* bb = b_warp_base0 + stage * stage_off;

#pragma unroll
        for (int ks = 0; ks < 2; ks++) {
            const int kb = ks * 8;
            uint32_t Ar[4][4], Br[4][2];
#pragma unroll
            for (int mf = 0; mf < 4; mf++) {
                const int r = mf * 16 + g;
                Ar[mf][0] = f2tf32(ab[r * PAD + kb + t4]);
                Ar[mf][1] = f2tf32(ab[(r + 8) * PAD + kb + t4]);
                Ar[mf][2] = f2tf32(ab[r * PAD + kb + t4 + 4]);
                Ar[mf][3] = f2tf32(ab[(r + 8) * PAD + kb + t4 + 4]);
            }
#pragma unroll
            for (int nf = 0; nf < 4; nf++) {
                const int c = nf * 8 + g;
                Br[nf][0] = f2tf32(bb[c * PAD + kb + t4]);
                Br[nf][1] = f2tf32(bb[c * PAD + kb + t4 + 4]);
            }
#pragma unroll
            for (int mf = 0; mf < 4; mf++)
#pragma unroll
                for (int nf = 0; nf < 4; nf++)
                    mma_tf32(acc[mf * 4 + nf], Ar[mf], Br[nf]);
        }
        __syncthreads();
        stage ^= 1;
    }

#pragma unroll
    for (int mf = 0; mf < 4; mf++) {
#pragma unroll
        for (int nf = 0; nf < 4; nf++) {
            const int idx = mf * 4 + nf;
            const int row = m0 + warpM * 64 + mf * 16 + g;
            const int col = n0 + warpN * 32 + nf * 8 + t4 * 2;
            float c0 = acc[idx][0], c1 = acc[idx][1];
            float c2 = acc[idx][2], c3 = acc[idx][3];
            if (ROUND) {
                c0 = __uint_as_float(f2tf32(c0));
                c1 = __uint_as_float(f2tf32(c1));
                c2 = __uint_as_float(f2tf32(c2));
                c3 = __uint_as_float(f2tf32(c3));
            }
            *(float2*)&C[(size_t)row * N + col]       = make_float2(c0, c1);
            *(float2*)&C[(size_t)(row + 8) * N + col] = make_float2(c2, c3);
        }
    }
}

// Fused Q/K/V projections: rounds outputs to tf32 values for attention.
__global__ __launch_bounds__(256) void gemm_tf32_qkv(
    const float* __restrict__ X,
    const float* __restrict__ Wq, const float* __restrict__ Wk,
    const float* __restrict__ Wv,
    float* __restrict__ Qo, float* __restrict__ Ko, float* __restrict__ Vo)
{
    __shared__ float As[2 * 128 * 20];
    __shared__ float Bs[2 * 128 * 20];
    const int z = blockIdx.z;
    const float* Bw = (z == 0) ? Wq : (z == 1) ? Wk : Wv;
    float* C = (z == 0) ? Qo : (z == 1) ? Ko : Vo;
    gemm_body<true>(X, Bw, C, MTOT, DMODEL, DMODEL,
                    blockIdx.y * 128, blockIdx.x * 128, As, Bs);
}

// Output projection (plain fp32 store).
__global__ __launch_bounds__(256) void gemm_tf32_out(
    const float* __restrict__ A, const float* __restrict__ Bw,
    float* __restrict__ C)
{
    __shared__ float As[2 * 128 * 20];
    __shared__ float Bs[2 * 128 * 20];
    gemm_body<false>(A, Bw, C, MTOT, DMODEL, DMODEL,
                     blockIdx.y * 128, blockIdx.x * 128, As, Bs);
}

// ---------------------------------------------------------------------------
// Tensor-core flash attention. Q/K/V hold tf32-valued fp32 (rounded by the
// QKV epilogue) -> all fragment loads are raw bits, no cvt.
// K/V tiles arrive via cp.async, double-buffered: zero LDG/STS instructions
// in the K/V path, one __syncthreads per tile. R7-proven conflict-free
// layouts: K row stride 68 words, V row stride 72 words.
// ---------------------------------------------------------------------------
#define AKS 68
#define AVS 72
#define KV_WORDS (64 * AKS + 64 * AVS)              // one stage
#define ATTN_SMEM_WORDS (2 * KV_WORDS + 128 * AKS)  // 26624 words = 104 KB
#define ATTN_SMEM_BYTES (ATTN_SMEM_WORDS * 4)

__global__ __launch_bounds__(256, 2) void attn_mma(
    const float* __restrict__ Q, const float* __restrict__ K,
    const float* __restrict__ V, float* __restrict__ Y)
{
    extern __shared__ float sm[];
    uint32_t* KV0 = (uint32_t*)sm;                 // stage 0: K[64*68] ++ V[64*72]
    uint32_t* KV1 = KV0 + KV_WORDS;                // stage 1
    float*    Ps  = (float*)(KV1 + KV_WORDS);      // [128][68] (Q staging / P)

    const int tid  = threadIdx.x;
    const int lane = tid & 31;
    const int warp = tid >> 5;
    const int g  = lane >> 2;   // 0..7
    const int t4 = lane & 3;    // 0..3
    const int mrow = warp * 16;

    const int qt = blockIdx.x;
    const int h  = blockIdx.y;
    const int b  = blockIdx.z;
    const size_t base = (size_t)b * SEQ * DMODEL + (size_t)h * DHEAD;

    // cp.async source/dest mapping: thread covers 16 floats of one K row and
    // one V row per tile (4 cp16 each).
    const int lrow = tid >> 2;         // 0..63
    const int lq   = (tid & 3) * 16;   // 0,16,32,48
    const float* Kg0 = &K[base + (size_t)lrow * DMODEL + lq];
    const float* Vg0 = &V[base + (size_t)lrow * DMODEL + lq];

    uint32_t kdst[2], vdst[2];
    kdst[0] = (uint32_t)__cvta_generic_to_shared(KV0 + lrow * AKS + lq);
    vdst[0] = (uint32_t)__cvta_generic_to_shared(KV0 + 64 * AKS + lrow * AVS + lq);
    kdst[1] = (uint32_t)__cvta_generic_to_shared(KV1 + lrow * AKS + lq);
    vdst[1] = (uint32_t)__cvta_generic_to_shared(KV1 + 64 * AKS + lrow * AVS + lq);

    // ---- Prologue: start tile 0 load; stage Q while it flies ----
#pragma unroll
    for (int i = 0; i < 4; i++) {
        cp16(kdst[0] + i * 16, Kg0 + i * 4);
        cp16(vdst[0] + i * 16, Vg0 + i * 4);
    }
    cp_commit();

    {
        const int r = tid >> 1;
        const int c0 = (tid & 1) * 32;
        const float* src = &Q[base + (size_t)(qt * 128 + r) * DMODEL + c0];
#pragma unroll
        for (int i = 0; i < 8; i++) {
            float4 v = *(const float4*)(src + i * 4);
            Ps[r * AKS + c0 + i * 4 + 0] = v.x * 0.125f;  // exact pow2 scale
            Ps[r * AKS + c0 + i * 4 + 1] = v.y * 0.125f;
            Ps[r * AKS + c0 + i * 4 + 2] = v.z * 0.125f;
            Ps[r * AKS + c0 + i * 4 + 3] = v.w * 0.125f;
        }
    }
    __syncthreads();

    uint32_t qf[8][4];
#pragma unroll
    for (int kb = 0; kb < 8; kb++) {
        qf[kb][0] = __float_as_uint(Ps[(mrow + g) * AKS + kb * 8 + t4]);
        qf[kb][1] = __float_as_uint(Ps[(mrow + g + 8) * AKS + kb * 8 + t4]);
        qf[kb][2] = __float_as_uint(Ps[(mrow + g) * AKS + kb * 8 + t4 + 4]);
        qf[kb][3] = __float_as_uint(Ps[(mrow + g + 8) * AKS + kb * 8 + t4 + 4]);
    }
    // (no barrier needed here: Ps rewritten only after the next barrier, and
    //  each warp writes/reads only its own Ps rows below)

    float o[8][4] = {};
    float m0r = -1e30f, m1r = -1e30f;
    float l0 = 0.0f, l1 = 0.0f;

    constexpr int NT = SEQ / 64;   // 32

    for (int kt = 0; kt < NT; kt++) {
        const int s = kt & 1;
        cp_wait<0>();        // tile kt resident in stage s
        __syncthreads();     // visible to all; all warps done reading stage s (from kt-2)

        // Launch tile kt+1 into the other stage (overlaps with compute below).
        if (kt + 1 < NT) {
            const float* Kg = Kg0 + (size_t)(kt + 1) * 64 * DMODEL;
            const float* Vg = Vg0 + (size_t)(kt + 1) * 64 * DMODEL;
            const int ns = s ^ 1;
#pragma unroll
            for (int i = 0; i < 4; i++) {
                cp16(kdst[ns] + i * 16, Kg + i * 4);
                cp16(vdst[ns] + i * 16, Vg + i * 4);
            }
            cp_commit();
        }

        const uint32_t* Ksu = (s == 0) ? KV0 : KV1;
        const uint32_t* Vsu = Ksu + 64 * AKS;

        // ---- S = Qs @ K^T  (16x64 per warp) ----
        float sacc[8][4] = {};
#pragma unroll
        for (int kb = 0; kb < 8; kb++) {
#pragma unroll
            for (int nf = 0; nf < 8; nf++) {
                uint32_t bf[2];
                bf[0] = Ksu[(nf * 8 + g) * AKS + kb * 8 + t4];
                bf[1] = Ksu[(nf * 8 + g) * AKS + kb * 8 + t4 + 4];
                mma_tf32(sacc[nf], qf[kb], bf);
            }
        }

        // ---- online softmax ----
        float rmax0 = -1e30f, rmax1 = -1e30f;
#pragma unroll
        for (int nf = 0; nf < 8; nf++) {
            rmax0 = fmaxf(rmax0, fmaxf(sacc[nf][0], sacc[nf][1]));
            rmax1 = fmaxf(rmax1, fmaxf(sacc[nf][2], sacc[nf][3]));
        }
        rmax0 = fmaxf(rmax0, __shfl_xor_sync(0xffffffffu, rmax0, 1));
        rmax0 = fmaxf(rmax0, __shfl_xor_sync(0xffffffffu, rmax0, 2));
        rmax1 = fmaxf(rmax1, __shfl_xor_sync(0xffffffffu, rmax1, 1));
        rmax1 = fmaxf(rmax1, __shfl_xor_sync(0xffffffffu, rmax1, 2));

        const float mnew0 = fmaxf(m0r, rmax0);
        const float mnew1 = fmaxf(m1r, rmax1);
        const float a0 = __expf(m0r - mnew0);
        const float a1 = __expf(m1r - mnew1);
        m0r = mnew0; m1r = mnew1;
        l0 *= a0;    l1 *= a1;

        float ps0 = 0.0f, ps1 = 0.0f;
#pragma unroll
        for (int nf = 0; nf < 8; nf++) {
            float p0 = __expf(sacc[nf][0] - m0r);
            float p1 = __expf(sacc[nf][1] - m0r);
            float p2 = __expf(sacc[nf][2] - m1r);
            float p3 = __expf(sacc[nf][3] - m1r);
            ps0 += p0 + p1;
            ps1 += p2 + p3;
            *(float2*)&Ps[(mrow + g) * AKS + nf * 8 + 2 * t4]     = make_float2(p0, p1);
            *(float2*)&Ps[(mrow + g + 8) * AKS + nf * 8 + 2 * t4] = make_float2(p2, p3);
            o[nf][0] *= a0; o[nf][1] *= a0;
            o[nf][2] *= a1; o[nf][3] *= a1;
        }
        l0 += ps0; l1 += ps1;
        __syncwarp();   // P visible within own warp (only own rows read)

        // ---- O += P @ V ----
#pragma unroll
        for (int kk = 0; kk < 8; kk++) {
            uint32_t pf[4];
            pf[0] = f2tf32(Ps[(mrow + g) * AKS + kk * 8 + t4]);
            pf[1] = f2tf32(Ps[(mrow + g + 8) * AKS + kk * 8 + t4]);
            pf[2] = f2tf32(Ps[(mrow + g) * AKS + kk * 8 + t4 + 4]);
            pf[3] = f2tf32(Ps[(mrow + g + 8) * AKS + kk * 8 + t4 + 4]);
#pragma unroll
            for (int nf = 0; nf < 8; nf++) {
                uint32_t vf[2];
                vf[0] = Vsu[(kk * 8 + t4) * AVS + nf * 8 + g];
                vf[1] = Vsu[(kk * 8 + t4 + 4) * AVS + nf * 8 + g];
                mma_tf32(o[nf], pf, vf);
            }
        }
        // no trailing barrier: next iteration's barrier (after cp_wait) is the
        // read-complete fence for this stage before it is overwritten (kt+2).
    }

    // ---- finalize ----
    l0 += __shfl_xor_sync(0xffffffffu, l0, 1);
    l0 += __shfl_xor_sync(0xffffffffu, l0, 2);
    l1 += __shfl_xor_sync(0xffffffffu, l1, 1);
    l1 += __shfl_xor_sync(0xffffffffu, l1, 2);
    const float inv0 = 1.0f / l0;
    const float inv1 = 1.0f / l1;

    const int row0 = qt * 128 + mrow + g;
#pragma unroll
    for (int nf = 0; nf < 8; nf++) {
        const int col = nf * 8 + 2 * t4;
        *(float2*)&Y[base + (size_t)row0 * DMODEL + col] =
            make_float2(o[nf][0] * inv0, o[nf][1] * inv0);
        *(float2*)&Y[base + (size_t)(row0 + 8) * DMODEL + col] =
            make_float2(o[nf][2] * inv1, o[nf][3] * inv1);
    }
}

// ---------------------------------------------------------------------------
extern "C" void kernel_launch(void* const* d_in, const int* in_sizes, int n_in,
                              void* d_out, int out_size)
{
    const float* X  = (const float*)d_in[0];
    const float* Wq = (const float*)d_in[1];
    const float* Wk = (const float*)d_in[2];
    const float* Wv = (const float*)d_in[3];
    const float* Wo = (const float*)d_in[4];
    float* out = (float*)d_out;

    float *pQ, *pK, *pV, *pY;
    cudaGetSymbolAddress((void**)&pQ, g_Q);
    cudaGetSymbolAddress((void**)&pK, g_K);
    cudaGetSymbolAddress((void**)&pV, g_V);
    cudaGetSymbolAddress((void**)&pY, g_Y);

    cudaFuncSetAttribute(attn_mma, cudaFuncAttributeMaxDynamicSharedMemorySize,
                         ATTN_SMEM_BYTES);

    dim3 gQKV(DMODEL / 128, MTOT / 128, 3);  // (8, 64, 3)
    gemm_tf32_qkv<<<gQKV, 256>>>(X, Wq, Wk, Wv, pQ, pK, pV);

    dim3 gAttn(SEQ / 128, NHEAD, BATCH);     // (16, 16, 4)
    attn_mma<<<gAttn, 256, ATTN_SMEM_BYTES>>>(pQ, pK, pV, pY);

    dim3 gGemm(DMODEL / 128, MTOT / 128);    // (8, 64)
    gemm_tf32_out<<<gGemm, 256>>>(pY, Wo, out);
}